// round 1
// baseline (speedup 1.0000x reference)
#include <cuda_runtime.h>
#include <math.h>

#define NN   20000
#define NP   20096      // 157 * 128 (padded rows)
#define EE   640000
#define FIN  128
#define HH   128
#define TT   12
#define NOUT 64
#define GI   384        // cin + 2H
#define G4   512        // 4 gates * H

// ---------------- scratch (device globals, no allocation) ----------------
__device__ float g_xT[(size_t)TT * NP * FIN];   // x transposed: [T][NP][FIN]
__device__ float g_h[2][(size_t)NP * HH];
__device__ float g_c[2][(size_t)NP * HH];
__device__ float g_xw[(size_t)NP * HH];
__device__ float g_g[(size_t)NP * HH];
__device__ float g_pre[(size_t)NP * G4];
__device__ float g_W4[2][GI * G4];
__device__ float g_b4[2][G4];
__device__ float g_deg[NN];
__device__ float g_dis[NN];
__device__ int   g_cnt[NN];
__device__ int   g_cur[NN];
__device__ int   g_ptr[NN + 1];
__device__ int   g_src[EE];
__device__ float g_wn[EE];

__device__ __forceinline__ float sigmoidf_(float x) { return 1.0f / (1.0f + expf(-x)); }

// ---------------- graph preprocessing ----------------
__global__ void k_init_nodes() {
    int i = blockIdx.x * blockDim.x + threadIdx.x;
    if (i < NN) { g_deg[i] = 1.0f; g_cnt[i] = 0; }   // self-loop weight 1
}

__global__ void k_edge_deg(const float* __restrict__ ea, const int* __restrict__ ei) {
    int e = blockIdx.x * blockDim.x + threadIdx.x;
    if (e < EE) {
        int c = ei[EE + e];
        atomicAdd(&g_deg[c], ea[4 * e + 3]);
        atomicAdd(&g_cnt[c], 1);
    }
}

__global__ void k_node_prep() {
    int i = blockIdx.x * blockDim.x + threadIdx.x;
    if (i < NN) { g_dis[i] = rsqrtf(g_deg[i]); g_cur[i] = 0; }
}

__global__ void k_scan() {
    __shared__ int sh[2][1024];
    __shared__ int carry;
    int tid = threadIdx.x;
    if (tid == 0) carry = 0;
    __syncthreads();
    for (int base = 0; base < NN; base += 1024) {
        int v = (base + tid < NN) ? g_cnt[base + tid] : 0;
        int buf = 0;
        sh[0][tid] = v;
        __syncthreads();
        for (int off = 1; off < 1024; off <<= 1) {
            int val = sh[buf][tid];
            if (tid >= off) val += sh[buf][tid - off];
            sh[buf ^ 1][tid] = val;
            buf ^= 1;
            __syncthreads();
        }
        int incl = sh[buf][tid];
        int c0 = carry;
        if (base + tid < NN) g_ptr[base + tid] = c0 + incl - v;   // exclusive
        __syncthreads();
        if (tid == 1023) carry = c0 + sh[buf][1023];
        __syncthreads();
    }
    if (tid == 0) g_ptr[NN] = carry;
}

__global__ void k_edge_fill(const float* __restrict__ ea, const int* __restrict__ ei) {
    int e = blockIdx.x * blockDim.x + threadIdx.x;
    if (e < EE) {
        int r = ei[e];
        int c = ei[EE + e];
        float w = ea[4 * e + 3];
        int pos = g_ptr[c] + atomicAdd(&g_cur[c], 1);
        g_src[pos] = r;
        g_wn[pos]  = g_dis[r] * w * g_dis[c];
    }
}

// ---------------- input transpose: x (N,F,T) -> xT [T][NP][F] ----------------
__global__ void k_transpose(const float* __restrict__ x) {
    long nf = (long)blockIdx.x * blockDim.x + threadIdx.x;
    if (nf >= (long)NN * FIN) return;
    float v[TT];
#pragma unroll
    for (int t = 0; t < TT; t++) v[t] = x[nf * TT + t];
#pragma unroll
    for (int t = 0; t < TT; t++) g_xT[(long)t * NP * FIN + nf] = v[t];
}

__global__ void k_zero_pads() {
    const int padN = (NP - NN) * FIN;       // 12288
    int i = blockIdx.x * blockDim.x + threadIdx.x;
    if (i < TT * padN) {
        int t = i / padN, r = i % padN;
        g_xT[(long)t * NP * FIN + (long)NN * FIN + r] = 0.0f;
    } else {
        int j = i - TT * padN;
        if (j < padN) g_g[(long)NN * HH + j] = 0.0f;
    }
}

__global__ void k_zero_state() {
    long i = (long)blockIdx.x * blockDim.x + threadIdx.x;
    if (i < (long)NP * HH) {
        g_h[0][i] = 0.0f; g_h[1][i] = 0.0f;
        g_c[0][i] = 0.0f; g_c[1][i] = 0.0f;
    }
}

// ---------------- pack gate weights into W4 [GI][G4] (f,i,o,c) ----------------
__global__ void k_buildW(const float* __restrict__ wf, const float* __restrict__ wi,
                         const float* __restrict__ wo, const float* __restrict__ wc,
                         const float* __restrict__ bf, const float* __restrict__ bi,
                         const float* __restrict__ bo, const float* __restrict__ bc,
                         int layer) {
    int idx = blockIdx.x * blockDim.x + threadIdx.x;
    if (idx >= GI * G4) return;
    int k = idx >> 9, col = idx & 511;
    int gsel = col >> 7, j = col & 127;
    const float* w = (gsel == 0) ? wf : (gsel == 1) ? wi : (gsel == 2) ? wo : wc;
    g_W4[layer][idx] = w[k * 128 + j];
    if (k == 0) {
        const float* b = (gsel == 0) ? bf : (gsel == 1) ? bi : (gsel == 2) ? bo : bc;
        g_b4[layer][col] = b[j];
    }
}

// ---------------- SGEMM: xw = A(NP x 128) @ B(128 x 128) ----------------
// BM=128 BN=128 BK=8, 256 threads, 8x8 per thread
__global__ __launch_bounds__(256) void k_gemm_in(int asel, const float* __restrict__ B) {
    const float* A = (asel >= 0) ? (g_xT + (long)asel * NP * FIN) : g_h[0];
    __shared__ float As[8][128];
    __shared__ float Bs[8][128];
    int bm = blockIdx.x * 128;
    int tid = threadIdx.x;
    int aRow = tid >> 1, aCol = (tid & 1) * 4;
    int bRow = tid >> 5, bCol = (tid & 31) * 4;
    int tm = (tid >> 4) * 8, tn = (tid & 15) * 8;
    float acc[8][8] = {};
    for (int k0 = 0; k0 < 128; k0 += 8) {
        float4 av = *(const float4*)(A + (long)(bm + aRow) * 128 + k0 + aCol);
        As[aCol + 0][aRow] = av.x; As[aCol + 1][aRow] = av.y;
        As[aCol + 2][aRow] = av.z; As[aCol + 3][aRow] = av.w;
        *(float4*)(&Bs[bRow][bCol]) = *(const float4*)(B + (long)(k0 + bRow) * 128 + bCol);
        __syncthreads();
#pragma unroll
        for (int k = 0; k < 8; k++) {
            float4 a0 = *(const float4*)&As[k][tm];
            float4 a1 = *(const float4*)&As[k][tm + 4];
            float4 b0 = *(const float4*)&Bs[k][tn];
            float4 b1 = *(const float4*)&Bs[k][tn + 4];
            float ar[8] = {a0.x, a0.y, a0.z, a0.w, a1.x, a1.y, a1.z, a1.w};
            float br[8] = {b0.x, b0.y, b0.z, b0.w, b1.x, b1.y, b1.z, b1.w};
#pragma unroll
            for (int i = 0; i < 8; i++)
#pragma unroll
                for (int j = 0; j < 8; j++) acc[i][j] += ar[i] * br[j];
        }
        __syncthreads();
    }
#pragma unroll
    for (int i = 0; i < 8; i++)
#pragma unroll
        for (int j = 0; j < 8; j += 4) {
            float4 o = {acc[i][j], acc[i][j + 1], acc[i][j + 2], acc[i][j + 3]};
            *(float4*)(&g_xw[(long)(bm + tm + i) * 128 + tn + j]) = o;
        }
}

// ---------------- SGEMM: pre = [in|g|h](NP x 384) @ W4(384 x 512) + b4 ----------------
__global__ __launch_bounds__(256) void k_gemm_gates(int asel, int layer) {
    const float* A0 = (asel >= 0) ? (g_xT + (long)asel * NP * FIN) : g_h[0];
    const float* A1 = g_g;
    const float* A2 = g_h[layer];
    const float* W  = g_W4[layer];
    const float* bias = g_b4[layer];
    __shared__ float As[8][128];
    __shared__ float Bs[8][128];
    int bm = blockIdx.x * 128;
    int bn = blockIdx.y * 128;
    int tid = threadIdx.x;
    int aRow = tid >> 1, aCol = (tid & 1) * 4;
    int bRow = tid >> 5, bCol = (tid & 31) * 4;
    int tm = (tid >> 4) * 8, tn = (tid & 15) * 8;
    float acc[8][8] = {};
    for (int k0 = 0; k0 < GI; k0 += 8) {
        const float* A = (k0 < 128) ? A0 : (k0 < 256 ? A1 : A2);
        int kk = k0 & 127;
        float4 av = *(const float4*)(A + (long)(bm + aRow) * 128 + kk + aCol);
        As[aCol + 0][aRow] = av.x; As[aCol + 1][aRow] = av.y;
        As[aCol + 2][aRow] = av.z; As[aCol + 3][aRow] = av.w;
        *(float4*)(&Bs[bRow][bCol]) = *(const float4*)(W + (long)(k0 + bRow) * G4 + bn + bCol);
        __syncthreads();
#pragma unroll
        for (int k = 0; k < 8; k++) {
            float4 a0 = *(const float4*)&As[k][tm];
            float4 a1 = *(const float4*)&As[k][tm + 4];
            float4 b0 = *(const float4*)&Bs[k][tn];
            float4 b1 = *(const float4*)&Bs[k][tn + 4];
            float ar[8] = {a0.x, a0.y, a0.z, a0.w, a1.x, a1.y, a1.z, a1.w};
            float br[8] = {b0.x, b0.y, b0.z, b0.w, b1.x, b1.y, b1.z, b1.w};
#pragma unroll
            for (int i = 0; i < 8; i++)
#pragma unroll
                for (int j = 0; j < 8; j++) acc[i][j] += ar[i] * br[j];
        }
        __syncthreads();
    }
#pragma unroll
    for (int i = 0; i < 8; i++)
#pragma unroll
        for (int j = 0; j < 8; j += 4) {
            float4 o = {acc[i][j]     + bias[bn + tn + j],
                        acc[i][j + 1] + bias[bn + tn + j + 1],
                        acc[i][j + 2] + bias[bn + tn + j + 2],
                        acc[i][j + 3] + bias[bn + tn + j + 3]};
            *(float4*)(&g_pre[(long)(bm + tm + i) * G4 + bn + tn + j]) = o;
        }
}

// ---------------- GCN aggregation + sigmoid ----------------
__global__ void k_aggregate(const float* __restrict__ gb) {
    int n = blockIdx.x;          // one node per block
    int f = threadIdx.x;         // 128 features
    float disn = g_dis[n];
    float acc = disn * disn * g_xw[(long)n * 128 + f];
    int s = g_ptr[n], e2 = g_ptr[n + 1];
    int p = s;
    for (; p + 4 <= e2; p += 4) {
        int  s0 = g_src[p],     s1 = g_src[p + 1], s2 = g_src[p + 2], s3 = g_src[p + 3];
        float w0 = g_wn[p],     w1 = g_wn[p + 1],  w2 = g_wn[p + 2],  w3 = g_wn[p + 3];
        float v0 = g_xw[(long)s0 * 128 + f];
        float v1 = g_xw[(long)s1 * 128 + f];
        float v2 = g_xw[(long)s2 * 128 + f];
        float v3 = g_xw[(long)s3 * 128 + f];
        acc += w0 * v0 + w1 * v1 + w2 * v2 + w3 * v3;
    }
    for (; p < e2; p++) acc += g_wn[p] * g_xw[(long)g_src[p] * 128 + f];
    acc += gb[f];
    g_g[(long)n * 128 + f] = sigmoidf_(acc);
}

// ---------------- LSTM pointwise ----------------
__global__ void k_pointwise(int layer) {
    long i = (long)blockIdx.x * blockDim.x + threadIdx.x;
    if (i >= (long)NP * HH) return;
    long n = i >> 7; int f = (int)(i & 127);
    const float* pre = &g_pre[n * G4];
    float ft = sigmoidf_(pre[f]);
    float it = sigmoidf_(pre[128 + f]);
    float ot = sigmoidf_(pre[256 + f]);
    float ct = tanhf(pre[384 + f]);
    float cn = ft * g_c[layer][i] + it * ct;
    g_c[layer][i] = cn;
    g_h[layer][i] = ot * tanhf(cn);
}

// ---------------- output projection ----------------
__global__ void k_out(const float* __restrict__ ow, const float* __restrict__ ob,
                      float* __restrict__ out) {
    __shared__ float hs[4][128];
    int r0 = blockIdx.x * 4;
    int tid = threadIdx.x;
    for (int idx = tid; idx < 512; idx += 256) {
        int rr = idx >> 7, kk = idx & 127;
        int n = r0 + rr;
        hs[rr][kk] = (n < NN) ? g_h[1][(long)n * 128 + kk] : 0.0f;
    }
    __syncthreads();
    int rr = tid >> 6, j = tid & 63;
    float acc = ob[j];
#pragma unroll 8
    for (int k = 0; k < 128; k++) acc += hs[rr][k] * ow[k * 64 + j];
    int n = r0 + rr;
    if (n < NN) out[(long)n * 64 + j] = acc;
}

// ---------------- launch ----------------
extern "C" void kernel_launch(void* const* d_in, const int* in_sizes, int n_in,
                              void* d_out, int out_size) {
    const float* x  = (const float*)d_in[0];
    const float* ea = (const float*)d_in[1];
    const int*   ei = (const int*)  d_in[2];
    const float* gw0 = (const float*)d_in[3];
    const float* gb0 = (const float*)d_in[4];
    const float* wf0 = (const float*)d_in[5];
    const float* bf0 = (const float*)d_in[6];
    const float* wi0 = (const float*)d_in[7];
    const float* bi0 = (const float*)d_in[8];
    const float* wo0 = (const float*)d_in[9];
    const float* bo0 = (const float*)d_in[10];
    const float* wc0 = (const float*)d_in[11];
    const float* bc0 = (const float*)d_in[12];
    const float* gw1 = (const float*)d_in[13];
    const float* gb1 = (const float*)d_in[14];
    const float* wf1 = (const float*)d_in[15];
    const float* bf1 = (const float*)d_in[16];
    const float* wi1 = (const float*)d_in[17];
    const float* bi1 = (const float*)d_in[18];
    const float* wo1 = (const float*)d_in[19];
    const float* bo1 = (const float*)d_in[20];
    const float* wc1 = (const float*)d_in[21];
    const float* bc1 = (const float*)d_in[22];
    const float* ow  = (const float*)d_in[23];
    const float* ob  = (const float*)d_in[24];
    float* out = (float*)d_out;

    // graph prep
    k_init_nodes<<<(NN + 255) / 256, 256>>>();
    k_edge_deg<<<EE / 256, 256>>>(ea, ei);
    k_node_prep<<<(NN + 255) / 256, 256>>>();
    k_scan<<<1, 1024>>>();
    k_edge_fill<<<EE / 256, 256>>>(ea, ei);

    // input transpose + zero init
    k_transpose<<<(NN * FIN + 255) / 256, 256>>>(x);
    {
        int tot = 13 * (NP - NN) * FIN;
        k_zero_pads<<<(tot + 255) / 256, 256>>>();
    }
    k_zero_state<<<((long)NP * HH + 255) / 256, 256>>>();

    // pack gate weights
    k_buildW<<<(GI * G4 + 255) / 256, 256>>>(wf0, wi0, wo0, wc0, bf0, bi0, bo0, bc0, 0);
    k_buildW<<<(GI * G4 + 255) / 256, 256>>>(wf1, wi1, wo1, wc1, bf1, bi1, bo1, bc1, 1);

    dim3 gGates(NP / 128, 4);
    dim3 gIn(NP / 128, 1);
    long pwThreads = (long)NP * HH;

    for (int t = 0; t < TT; t++) {
        // layer 0: input = xT[t]
        k_gemm_in<<<gIn, 256>>>(t, gw0);
        k_aggregate<<<NN, 128>>>(gb0);
        k_gemm_gates<<<gGates, 256>>>(t, 0);
        k_pointwise<<<(pwThreads + 255) / 256, 256>>>(0);
        // layer 1: input = h0
        k_gemm_in<<<gIn, 256>>>(-1, gw1);
        k_aggregate<<<NN, 128>>>(gb1);
        k_gemm_gates<<<gGates, 256>>>(-1, 1);
        k_pointwise<<<(pwThreads + 255) / 256, 256>>>(1);
    }

    k_out<<<(NN + 3) / 4, 256>>>(ow, ob, out);
}

// round 3
// speedup vs baseline: 2.3800x; 2.3800x over previous
#include <cuda_runtime.h>
#include <cuda_bf16.h>
#include <math.h>
#include <stdint.h>

#define NN   20000
#define NP   20096      // 157 * 128 (padded rows)
#define EE   640000
#define FIN  128
#define HH   128
#define TT   12
#define NOUT 64
#define GI   384        // cin + 2H
#define G4   512        // 4 gates * H

// ---------------- scratch (device globals, no allocation) ----------------
__device__ __nv_bfloat16 g_xh_hi[(size_t)TT * NP * FIN];
__device__ __nv_bfloat16 g_xh_lo[(size_t)TT * NP * FIN];
__device__ float         g_h[2][(size_t)NP * HH];
__device__ __nv_bfloat16 g_h_hi[2][(size_t)NP * HH];
__device__ __nv_bfloat16 g_h_lo[2][(size_t)NP * HH];
__device__ float         g_c[2][(size_t)NP * HH];
__device__ float         g_xw[(size_t)NP * HH];
__device__ __nv_bfloat16 g_g_hi[(size_t)NP * HH];
__device__ __nv_bfloat16 g_g_lo[(size_t)NP * HH];
__device__ float         g_pre[(size_t)NP * G4];
__device__ __nv_bfloat16 g_Wt_hi[2][G4 * GI];   // [n=512][k=384]
__device__ __nv_bfloat16 g_Wt_lo[2][G4 * GI];
__device__ __nv_bfloat16 g_gwT_hi[2][HH * HH];  // [n=128][k=128]
__device__ __nv_bfloat16 g_gwT_lo[2][HH * HH];
__device__ float         g_b4[2][G4];
__device__ float g_deg[NN];
__device__ float g_dis[NN];
__device__ int   g_cnt[NN];
__device__ int   g_cur[NN];
__device__ int   g_ptr[NN + 1];
__device__ int   g_src[EE];
__device__ float g_wn[EE];

__device__ __forceinline__ float sigmoidf_(float x) { return 1.0f / (1.0f + expf(-x)); }

__device__ __forceinline__ void split_bf16(float v, __nv_bfloat16& hi, __nv_bfloat16& lo) {
    hi = __float2bfloat16(v);
    lo = __float2bfloat16(v - __bfloat162float(hi));
}

// ---------------- mma helpers (arch-portable: sm_80+ ISA only) ----------------
__device__ __forceinline__ uint32_t smem_u32(const void* p) {
    return (uint32_t)__cvta_generic_to_shared(p);
}
__device__ __forceinline__ uint32_t swz128(uint32_t o) { return o ^ ((o >> 3) & 0x70); }

__device__ __forceinline__ void cp16(uint32_t dst, const void* src) {
    asm volatile("cp.async.cg.shared.global [%0], [%1], 16;" :: "r"(dst), "l"(src));
}
__device__ __forceinline__ void ldm4(uint32_t* r, uint32_t addr) {
    asm volatile("ldmatrix.sync.aligned.m8n8.x4.shared.b16 {%0,%1,%2,%3}, [%4];"
                 : "=r"(r[0]), "=r"(r[1]), "=r"(r[2]), "=r"(r[3]) : "r"(addr));
}
__device__ __forceinline__ void mma16816(float* c, const uint32_t* a, const uint32_t* b) {
    asm volatile("mma.sync.aligned.m16n8k16.row.col.f32.bf16.bf16.f32 "
                 "{%0,%1,%2,%3}, {%4,%5,%6,%7}, {%8,%9}, {%0,%1,%2,%3};"
                 : "+f"(c[0]), "+f"(c[1]), "+f"(c[2]), "+f"(c[3])
                 : "r"(a[0]), "r"(a[1]), "r"(a[2]), "r"(a[3]), "r"(b[0]), "r"(b[1]));
}

// ---------------- graph preprocessing ----------------
__global__ void k_init_nodes() {
    int i = blockIdx.x * blockDim.x + threadIdx.x;
    if (i < NN) { g_deg[i] = 1.0f; g_cnt[i] = 0; }
}
__global__ void k_edge_deg(const float* __restrict__ ea, const int* __restrict__ ei) {
    int e = blockIdx.x * blockDim.x + threadIdx.x;
    if (e < EE) {
        int c = ei[EE + e];
        atomicAdd(&g_deg[c], ea[4 * e + 3]);
        atomicAdd(&g_cnt[c], 1);
    }
}
__global__ void k_node_prep() {
    int i = blockIdx.x * blockDim.x + threadIdx.x;
    if (i < NN) { g_dis[i] = rsqrtf(g_deg[i]); g_cur[i] = 0; }
}
__global__ void k_scan() {
    __shared__ int sh[2][1024];
    __shared__ int carry;
    int tid = threadIdx.x;
    if (tid == 0) carry = 0;
    __syncthreads();
    for (int base = 0; base < NN; base += 1024) {
        int v = (base + tid < NN) ? g_cnt[base + tid] : 0;
        int buf = 0;
        sh[0][tid] = v;
        __syncthreads();
        for (int off = 1; off < 1024; off <<= 1) {
            int val = sh[buf][tid];
            if (tid >= off) val += sh[buf][tid - off];
            sh[buf ^ 1][tid] = val;
            buf ^= 1;
            __syncthreads();
        }
        int incl = sh[buf][tid];
        int c0 = carry;
        if (base + tid < NN) g_ptr[base + tid] = c0 + incl - v;
        __syncthreads();
        if (tid == 1023) carry = c0 + sh[buf][1023];
        __syncthreads();
    }
    if (tid == 0) g_ptr[NN] = carry;
}
__global__ void k_edge_fill(const float* __restrict__ ea, const int* __restrict__ ei) {
    int e = blockIdx.x * blockDim.x + threadIdx.x;
    if (e < EE) {
        int r = ei[e];
        int c = ei[EE + e];
        float w = ea[4 * e + 3];
        int pos = g_ptr[c] + atomicAdd(&g_cur[c], 1);
        g_src[pos] = r;
        g_wn[pos]  = g_dis[r] * w * g_dis[c];
    }
}

// ---------------- input transpose + split ----------------
__global__ void k_transpose(const float* __restrict__ x) {
    long nf = (long)blockIdx.x * blockDim.x + threadIdx.x;
    if (nf >= (long)NN * FIN) return;
    float v[TT];
#pragma unroll
    for (int t = 0; t < TT; t++) v[t] = x[nf * TT + t];
#pragma unroll
    for (int t = 0; t < TT; t++) {
        __nv_bfloat16 hi, lo;
        split_bf16(v[t], hi, lo);
        g_xh_hi[(long)t * NP * FIN + nf] = hi;
        g_xh_lo[(long)t * NP * FIN + nf] = lo;
    }
}

__global__ void k_zero_pads() {
    const int padN = (NP - NN) * FIN;   // 12288
    int i = blockIdx.x * blockDim.x + threadIdx.x;
    __nv_bfloat16 z = __float2bfloat16(0.0f);
    if (i < TT * padN) {
        int t = i / padN, r = i % padN;
        long o = (long)t * NP * FIN + (long)NN * FIN + r;
        g_xh_hi[o] = z; g_xh_lo[o] = z;
    } else {
        int j = i - TT * padN;
        if (j < padN) {
            long o = (long)NN * FIN + j;
            g_g_hi[o] = z; g_g_lo[o] = z;
        }
    }
}

__global__ void k_zero_state() {
    long i = (long)blockIdx.x * blockDim.x + threadIdx.x;
    if (i < (long)NP * HH) {
        __nv_bfloat16 z = __float2bfloat16(0.0f);
        g_h[0][i] = 0.0f; g_h[1][i] = 0.0f;
        g_c[0][i] = 0.0f; g_c[1][i] = 0.0f;
        g_h_hi[0][i] = z; g_h_hi[1][i] = z;
        g_h_lo[0][i] = z; g_h_lo[1][i] = z;
    }
}

// ---------------- pack gate weights: Wt[n=512][k=384] bf16 hi/lo ----------------
__global__ void k_buildW(const float* __restrict__ wf, const float* __restrict__ wi,
                         const float* __restrict__ wo, const float* __restrict__ wc,
                         const float* __restrict__ bf, const float* __restrict__ bi,
                         const float* __restrict__ bo, const float* __restrict__ bc,
                         int layer) {
    int idx = blockIdx.x * blockDim.x + threadIdx.x;
    if (idx >= G4 * GI) return;
    int n = idx / GI, k = idx % GI;
    int gsel = n >> 7, j = n & 127;
    const float* w = (gsel == 0) ? wf : (gsel == 1) ? wi : (gsel == 2) ? wo : wc;
    __nv_bfloat16 hi, lo;
    split_bf16(w[k * 128 + j], hi, lo);
    g_Wt_hi[layer][idx] = hi;
    g_Wt_lo[layer][idx] = lo;
    if (k == 0) {
        const float* b = (gsel == 0) ? bf : (gsel == 1) ? bi : (gsel == 2) ? bo : bc;
        g_b4[layer][n] = b[j];
    }
}

__global__ void k_buildGW(const float* __restrict__ gw, int layer) {
    int idx = blockIdx.x * blockDim.x + threadIdx.x;
    if (idx >= HH * HH) return;
    int n = idx >> 7, k = idx & 127;
    __nv_bfloat16 hi, lo;
    split_bf16(gw[k * 128 + n], hi, lo);
    g_gwT_hi[layer][idx] = hi;
    g_gwT_lo[layer][idx] = lo;
}

// ================= MMA GEMM (bf16 split, 3 passes) ====================
// Tile 128(M) x 128(N), K chunks of 64, cp.async double-buffered.
// smem buffer layout (64KB each, x2): Ahi 16K | Alo 16K | Bhi 16K | Blo 16K
// GATES: C(NP x 512) = [x|g|h](NP x 384) @ Wt^T, +bias -> g_pre
// !GATES: C(NP x 128) = A(NP x 128) @ gwT^T -> g_xw
#define MMA_SMEM (2 * 65536)

template<bool GATES>
__global__ __launch_bounds__(256) void k_mma(int asel, int layer) {
    extern __shared__ char smem[];
    uint32_t sb = smem_u32(smem);
    int tid = threadIdx.x, wid = tid >> 5, lane = tid & 31;
    int bm = blockIdx.x * 128, bn = blockIdx.y * 128;
    const int NCH = GATES ? 6 : 2;
    const int ldk = GATES ? GI : HH;
    const __nv_bfloat16* Bh = GATES ? g_Wt_hi[layer] : g_gwT_hi[layer];
    const __nv_bfloat16* Bl = GATES ? g_Wt_lo[layer] : g_gwT_lo[layer];
    const __nv_bfloat16* inp_hi = (asel >= 0) ? g_xh_hi + (size_t)asel * NP * FIN : g_h_hi[0];
    const __nv_bfloat16* inp_lo = (asel >= 0) ? g_xh_lo + (size_t)asel * NP * FIN : g_h_lo[0];

    auto load_chunk = [&](int c) {
        uint32_t bo = sb + (uint32_t)(c & 1) * 65536u;
        const __nv_bfloat16 *ah, *al;
        int cofs;
        if (GATES) {
            int half = c >> 1;
            ah = (half == 0) ? inp_hi : (half == 1) ? g_g_hi : g_h_hi[layer];
            al = (half == 0) ? inp_lo : (half == 1) ? g_g_lo : g_h_lo[layer];
            cofs = (c & 1) * 64;
        } else {
            ah = inp_hi; al = inp_lo; cofs = c * 64;
        }
        int bk = c * 64;
#pragma unroll
        for (int i = tid; i < 1024; i += 256) {
            int r = i >> 3, j = i & 7;
            uint32_t so = swz128((uint32_t)r * 128 + j * 16);
            cp16(bo + so,         ah + (size_t)(bm + r) * FIN + cofs + j * 8);
            cp16(bo + 16384 + so, al + (size_t)(bm + r) * FIN + cofs + j * 8);
            cp16(bo + 32768 + so, Bh + (size_t)(bn + r) * ldk + bk + j * 8);
            cp16(bo + 49152 + so, Bl + (size_t)(bn + r) * ldk + bk + j * 8);
        }
        asm volatile("cp.async.commit_group;" ::: "memory");
    };

    float acc[4][4][4];
#pragma unroll
    for (int a = 0; a < 4; a++)
#pragma unroll
        for (int b = 0; b < 4; b++)
#pragma unroll
            for (int r = 0; r < 4; r++) acc[a][b][r] = 0.0f;

    int m0 = (wid & 1) * 64, n0 = (wid >> 1) * 32;
    int a_lr = ((lane >> 3) & 1) * 8 + (lane & 7);
    int a_cb = (lane >> 4) * 16;
    int b_lr = (lane >> 4) * 8 + (lane & 7);
    int b_cb = ((lane >> 3) & 1) * 16;

    load_chunk(0);
    for (int c = 0; c < NCH; c++) {
        if (c + 1 < NCH) {
            load_chunk(c + 1);
            asm volatile("cp.async.wait_group 1;" ::: "memory");
        } else {
            asm volatile("cp.async.wait_group 0;" ::: "memory");
        }
        __syncthreads();
        uint32_t base = sb + (uint32_t)(c & 1) * 65536u;
#pragma unroll
        for (int ks = 0; ks < 4; ks++) {
            int kb = ks * 32;
            uint32_t ah[4][4], al[4][4], bh[4][2], bl[4][2];
#pragma unroll
            for (int mf = 0; mf < 4; mf++) {
                int row = m0 + mf * 16 + a_lr;
                uint32_t off = (uint32_t)row * 128 + (((uint32_t)(kb + a_cb)) ^ ((row & 7) << 4));
                ldm4(ah[mf], base + off);
                ldm4(al[mf], base + 16384 + off);
            }
#pragma unroll
            for (int np = 0; np < 2; np++) {
                int row = n0 + np * 16 + b_lr;
                uint32_t off = (uint32_t)row * 128 + (((uint32_t)(kb + b_cb)) ^ ((row & 7) << 4));
                uint32_t t[4];
                ldm4(t, base + 32768 + off);
                bh[np * 2][0] = t[0]; bh[np * 2][1] = t[1];
                bh[np * 2 + 1][0] = t[2]; bh[np * 2 + 1][1] = t[3];
                ldm4(t, base + 49152 + off);
                bl[np * 2][0] = t[0]; bl[np * 2][1] = t[1];
                bl[np * 2 + 1][0] = t[2]; bl[np * 2 + 1][1] = t[3];
            }
#pragma unroll
            for (int mf = 0; mf < 4; mf++)
#pragma unroll
                for (int nf = 0; nf < 4; nf++) mma16816(acc[mf][nf], ah[mf], bh[nf]);
#pragma unroll
            for (int mf = 0; mf < 4; mf++)
#pragma unroll
                for (int nf = 0; nf < 4; nf++) mma16816(acc[mf][nf], ah[mf], bl[nf]);
#pragma unroll
            for (int mf = 0; mf < 4; mf++)
#pragma unroll
                for (int nf = 0; nf < 4; nf++) mma16816(acc[mf][nf], al[mf], bh[nf]);
        }
        __syncthreads();
    }

    // epilogue
    int tq = lane >> 2, tr = (lane & 3) * 2;
    if (GATES) {
        const float* bias = g_b4[layer];
#pragma unroll
        for (int mf = 0; mf < 4; mf++)
#pragma unroll
            for (int nf = 0; nf < 4; nf++) {
                int row = bm + m0 + mf * 16 + tq;
                int col = bn + n0 + nf * 8 + tr;
                float b0 = bias[col], b1 = bias[col + 1];
                *(float2*)(g_pre + (size_t)row * G4 + col) =
                    make_float2(acc[mf][nf][0] + b0, acc[mf][nf][1] + b1);
                *(float2*)(g_pre + (size_t)(row + 8) * G4 + col) =
                    make_float2(acc[mf][nf][2] + b0, acc[mf][nf][3] + b1);
            }
    } else {
#pragma unroll
        for (int mf = 0; mf < 4; mf++)
#pragma unroll
            for (int nf = 0; nf < 4; nf++) {
                int row = bm + m0 + mf * 16 + tq;
                int col = bn + n0 + nf * 8 + tr;
                *(float2*)(g_xw + (size_t)row * HH + col) =
                    make_float2(acc[mf][nf][0], acc[mf][nf][1]);
                *(float2*)(g_xw + (size_t)(row + 8) * HH + col) =
                    make_float2(acc[mf][nf][2], acc[mf][nf][3]);
            }
    }
}

// ---------------- GCN aggregation + sigmoid -> g bf16 hi/lo ----------------
__global__ void k_aggregate(const float* __restrict__ gb) {
    int n = blockIdx.x;
    int f = threadIdx.x;
    float disn = g_dis[n];
    float acc = disn * disn * g_xw[(long)n * 128 + f];
    int e2 = g_ptr[n + 1];
    int p = g_ptr[n];
    for (; p + 4 <= e2; p += 4) {
        int  s0 = g_src[p],     s1 = g_src[p + 1], s2 = g_src[p + 2], s3 = g_src[p + 3];
        float w0 = g_wn[p],     w1 = g_wn[p + 1],  w2 = g_wn[p + 2],  w3 = g_wn[p + 3];
        acc += w0 * g_xw[(long)s0 * 128 + f];
        acc += w1 * g_xw[(long)s1 * 128 + f];
        acc += w2 * g_xw[(long)s2 * 128 + f];
        acc += w3 * g_xw[(long)s3 * 128 + f];
    }
    for (; p < e2; p++) acc += g_wn[p] * g_xw[(long)g_src[p] * 128 + f];
    acc += gb[f];
    float s = sigmoidf_(acc);
    __nv_bfloat16 hi, lo;
    split_bf16(s, hi, lo);
    g_g_hi[(long)n * 128 + f] = hi;
    g_g_lo[(long)n * 128 + f] = lo;
}

// ---------------- LSTM pointwise ----------------
__global__ void k_pointwise(int layer) {
    long i = (long)blockIdx.x * blockDim.x + threadIdx.x;
    if (i >= (long)NP * HH) return;
    long n = i >> 7; int f = (int)(i & 127);
    const float* pre = &g_pre[n * G4];
    float ft = sigmoidf_(pre[f]);
    float it = sigmoidf_(pre[128 + f]);
    float ot = sigmoidf_(pre[256 + f]);
    float ct = tanhf(pre[384 + f]);
    float cn = ft * g_c[layer][i] + it * ct;
    g_c[layer][i] = cn;
    float hn = ot * tanhf(cn);
    g_h[layer][i] = hn;
    __nv_bfloat16 hi, lo;
    split_bf16(hn, hi, lo);
    g_h_hi[layer][i] = hi;
    g_h_lo[layer][i] = lo;
}

// ---------------- output projection ----------------
__global__ void k_out(const float* __restrict__ ow, const float* __restrict__ ob,
                      float* __restrict__ out) {
    __shared__ float hs[4][128];
    int r0 = blockIdx.x * 4;
    int tid = threadIdx.x;
    for (int idx = tid; idx < 512; idx += 256) {
        int rr = idx >> 7, kk = idx & 127;
        int n = r0 + rr;
        hs[rr][kk] = (n < NN) ? g_h[1][(long)n * 128 + kk] : 0.0f;
    }
    __syncthreads();
    int rr = tid >> 6, j = tid & 63;
    float acc = ob[j];
#pragma unroll 8
    for (int k = 0; k < 128; k++) acc += hs[rr][k] * ow[k * 64 + j];
    int n = r0 + rr;
    if (n < NN) out[(long)n * 64 + j] = acc;
}

// ---------------- launch ----------------
extern "C" void kernel_launch(void* const* d_in, const int* in_sizes, int n_in,
                              void* d_out, int out_size) {
    const float* x  = (const float*)d_in[0];
    const float* ea = (const float*)d_in[1];
    const int*   ei = (const int*)  d_in[2];
    const float* gw0 = (const float*)d_in[3];
    const float* gb0 = (const float*)d_in[4];
    const float* wf0 = (const float*)d_in[5];
    const float* bf0 = (const float*)d_in[6];
    const float* wi0 = (const float*)d_in[7];
    const float* bi0 = (const float*)d_in[8];
    const float* wo0 = (const float*)d_in[9];
    const float* bo0 = (const float*)d_in[10];
    const float* wc0 = (const float*)d_in[11];
    const float* bc0 = (const float*)d_in[12];
    const float* gw1 = (const float*)d_in[13];
    const float* gb1 = (const float*)d_in[14];
    const float* wf1 = (const float*)d_in[15];
    const float* bf1 = (const float*)d_in[16];
    const float* wi1 = (const float*)d_in[17];
    const float* bi1 = (const float*)d_in[18];
    const float* wo1 = (const float*)d_in[19];
    const float* bo1 = (const float*)d_in[20];
    const float* wc1 = (const float*)d_in[21];
    const float* bc1 = (const float*)d_in[22];
    const float* ow  = (const float*)d_in[23];
    const float* ob  = (const float*)d_in[24];
    float* out = (float*)d_out;

    cudaFuncSetAttribute(k_mma<true>,  cudaFuncAttributeMaxDynamicSharedMemorySize, MMA_SMEM);
    cudaFuncSetAttribute(k_mma<false>, cudaFuncAttributeMaxDynamicSharedMemorySize, MMA_SMEM);

    // graph prep
    k_init_nodes<<<(NN + 255) / 256, 256>>>();
    k_edge_deg<<<EE / 256, 256>>>(ea, ei);
    k_node_prep<<<(NN + 255) / 256, 256>>>();
    k_scan<<<1, 1024>>>();
    k_edge_fill<<<EE / 256, 256>>>(ea, ei);

    // input transpose + split, zero init
    k_transpose<<<(NN * FIN + 255) / 256, 256>>>(x);
    {
        int tot = (TT + 1) * (NP - NN) * FIN;
        k_zero_pads<<<(tot + 255) / 256, 256>>>();
    }
    k_zero_state<<<((long)NP * HH + 255) / 256, 256>>>();

    // pack weights (bf16 split)
    k_buildW<<<(G4 * GI + 255) / 256, 256>>>(wf0, wi0, wo0, wc0, bf0, bi0, bo0, bc0, 0);
    k_buildW<<<(G4 * GI + 255) / 256, 256>>>(wf1, wi1, wo1, wc1, bf1, bi1, bo1, bc1, 1);
    k_buildGW<<<(HH * HH + 255) / 256, 256>>>(gw0, 0);
    k_buildGW<<<(HH * HH + 255) / 256, 256>>>(gw1, 1);

    dim3 gGates(NP / 128, G4 / 128);
    dim3 gGcn(NP / 128, 1);
    long pwThreads = (long)NP * HH;

    for (int t = 0; t < TT; t++) {
        // layer 0: input = x[t]
        k_mma<false><<<gGcn, 256, MMA_SMEM>>>(t, 0);
        k_aggregate<<<NN, 128>>>(gb0);
        k_mma<true><<<gGates, 256, MMA_SMEM>>>(t, 0);
        k_pointwise<<<(pwThreads + 255) / 256, 256>>>(0);
        // layer 1: input = h0
        k_mma<false><<<gGcn, 256, MMA_SMEM>>>(-1, 1);
        k_aggregate<<<NN, 128>>>(gb1);
        k_mma<true><<<gGates, 256, MMA_SMEM>>>(-1, 1);
        k_pointwise<<<(pwThreads + 255) / 256, 256>>>(1);
    }

    k_out<<<(NN + 3) / 4, 256>>>(ow, ob, out);
}